// round 17
// baseline (speedup 1.0000x reference)
#include <cuda_runtime.h>

#define F 96
#define C4 24               // float4 chunks per feature row
#define CAPN 50240          // node capacity (N = 50000)
#define FULLM 0xffffffffu
#define ET 64               // edges per scatter tile
#define GR 64               // gemm rows per block

// swizzled smem layout for a 48-column half of W: [jlocal][k]
// lane stride (6 cols) = 604 floats = 151 16B-units == 7 (mod 8) -> conflict-free
#define WTOFF(j, k) ((j) * 100 + ((j) / 6) * 4 + (k))
#define WT_FLOATS (WTOFF(47, 96) + 4)          // 4828 floats ~ 19.3KB

// ---- scratch (__device__ globals; accessed ONLY by name in device code) ----
__device__ int    g_degi[CAPN];        // zeroed statically; re-zeroed in gemm1
__device__ float  g_dinv[CAPN];
__device__ float4 g_agg1[CAPN * C4];   // scatter target 1
__device__ float4 g_h1s [CAPN * C4];   // relu((A x)@W1 + b1)  (unscaled)
__device__ float4 g_agg2[CAPN * C4];   // scatter target 2

template <int SEL> __device__ __forceinline__ float4* buf();
template <> __device__ __forceinline__ float4* buf<1>() { return g_agg1; }
template <> __device__ __forceinline__ float4* buf<3>() { return g_agg2; }

__device__ __forceinline__ void red4(float4* p, float4 v) { atomicAdd(p, v); }

// packed f32x2 fma: a += v * m  (lanes independent)
__device__ __forceinline__ void fma2(unsigned long long& a,
                                     unsigned long long v,
                                     unsigned long long m) {
    asm volatile("fma.rn.f32x2 %0, %1, %2, %0;" : "+l"(a) : "l"(v), "l"(m));
}
__device__ __forceinline__ float sum2(unsigned long long a) {
    float2 f = *reinterpret_cast<float2*>(&a);
    return f.x + f.y;
}

// ---------------------------------------------------------------------------
// launch 0: degree by dst (warp-aggregated for hub) + zero both agg buffers
// (independent side-job, grid-strided over this kernel's 900k threads)
// ---------------------------------------------------------------------------
__global__ void deg_kernel(const int* __restrict__ dst, int E, int N) {
    int e = blockIdx.x * blockDim.x + threadIdx.x;

    {   // zero agg1 + agg2 (no dependency on degrees)
        int n4 = N * C4;
        int nt = gridDim.x * blockDim.x;
        float4 z = make_float4(0.f, 0.f, 0.f, 0.f);
        for (int i = e; i < n4; i += nt) { g_agg1[i] = z; g_agg2[i] = z; }
    }

    bool valid = e < E;
    int d = valid ? dst[e] : -1;
    int d0 = __shfl_sync(FULLM, d, 0);
    unsigned bal = __ballot_sync(FULLM, valid && d == d0);
    if (bal == FULLM) {
        if ((threadIdx.x & 31) == 0) atomicAdd(&g_degi[d0], 32);
    } else if (valid) {
        atomicAdd(&g_degi[d], 1);
    }
}

// ---------------------------------------------------------------------------
// launch 1: dinv from degi (tiny)
// ---------------------------------------------------------------------------
__global__ void dinv_kernel(int N) {
    int i = blockIdx.x * blockDim.x + threadIdx.x;
    if (i < N) {
        int dg = g_degi[i];
        g_dinv[i] = dg > 0 ? rsqrtf(fmaxf((float)dg, 1.f)) : 0.f;
    }
}

// ---------------------------------------------------------------------------
// Scatter: agg[dst] += dinv[src] * feat[src]
// 192 threads = 8 edge-slots x 24 chunks; 64-edge tiles staged in smem
// (src, dst, dinv[src]). Uniform-dst (hub) tiles -> 1 atomic per chunk.
// ---------------------------------------------------------------------------
template <bool USEH1, int OUT>
__global__ void __launch_bounds__(192) scatter_kernel(
        const int* __restrict__ src, const int* __restrict__ dst,
        const float4* __restrict__ xfeat, int E) {
    const float4* __restrict__ feat = USEH1 ? g_h1s : xfeat;
    float4* __restrict__ agg = buf<OUT>();

    const int t = threadIdx.x;
    const int c = t % C4;               // chunk 0..23
    const int g = t / C4;               // edge slot 0..7
    __shared__ int    ss[ET], sd[ET];
    __shared__ float  sn[ET];
    __shared__ int    s_uni;
    __shared__ float4 sred[192];

    const int base = blockIdx.x * ET;
    const int m = min(ET, E - base);

    if (t == 0) s_uni = (m == ET) ? 1 : 0;
    if (t < m) {
        int s = src[base + t];
        ss[t] = s;
        sd[t] = dst[base + t];
        sn[t] = g_dinv[s];
    }
    __syncthreads();
    if (t < m && sd[t] != sd[0]) s_uni = 0;
    __syncthreads();

    if (s_uni) {
        float4 acc = make_float4(0.f, 0.f, 0.f, 0.f);
#pragma unroll
        for (int r = 0; r < 8; r++) {
            int j = r * 8 + g;
            float nm = sn[j];
            float4 v = __ldg(feat + (size_t)ss[j] * C4 + c);
            acc.x = fmaf(nm, v.x, acc.x); acc.y = fmaf(nm, v.y, acc.y);
            acc.z = fmaf(nm, v.z, acc.z); acc.w = fmaf(nm, v.w, acc.w);
        }
        sred[t] = acc;
        __syncthreads();
        if (g == 0) {
#pragma unroll
            for (int k = 1; k < 8; k++) {
                float4 v = sred[k * C4 + c];
                acc.x += v.x; acc.y += v.y; acc.z += v.z; acc.w += v.w;
            }
            red4(agg + (size_t)sd[0] * C4 + c, acc);
        }
    } else {
#pragma unroll
        for (int r = 0; r < 8; r++) {
            int j = r * 8 + g;
            if (j < m) {
                float nm = sn[j];
                float4 v = __ldg(feat + (size_t)ss[j] * C4 + c);
                v.x *= nm; v.y *= nm; v.z *= nm; v.w *= nm;
                red4(agg + (size_t)sd[j] * C4 + c, v);
            }
        }
    }
}

// ---------------------------------------------------------------------------
// Register-tiled GEMM: block = 64 rows x 48 cols (half of W), 128 threads.
// Thread tile = 4 rows x 6 cols; rowg = t>>3 (16), colg = t&7 (8).
// W half in static smem (swizzled); x rows read via __ldg with software
// pipelining (next k-chunk prefetched during current chunk's FMAs).
// dinv[row] factored out of the dot product, applied in the epilogue.
// ---------------------------------------------------------------------------
__device__ __forceinline__ void load_wt_half(float* Wt,
                                             const float* __restrict__ W,
                                             int colhalf, int t) {
    const float4* __restrict__ W4 = (const float4*)W;
    for (int i = t; i < F * 12; i += 128) {      // k = i/12, local col grp = i%12
        int k = i / 12, cg = i % 12;
        float4 w = __ldg(W4 + k * C4 + colhalf * 12 + cg);
        int j = cg * 4;
        Wt[WTOFF(j + 0, k)] = w.x;
        Wt[WTOFF(j + 1, k)] = w.y;
        Wt[WTOFF(j + 2, k)] = w.z;
        Wt[WTOFF(j + 3, k)] = w.w;
    }
}

// 4 rows x 6 cols; acc[r*6+c] packed over k-parity; x via __ldg, pipelined
__device__ __forceinline__ void mmkern(const float* Wt,
                                       const float4* __restrict__ feat,
                                       int row0t, int colL0,
                                       unsigned long long acc[24]) {
    ulonglong2 xv[4], xn[4];
#pragma unroll
    for (int r = 0; r < 4; r++)
        xv[r] = __ldg((const ulonglong2*)(feat + (size_t)(row0t + r) * C4));
#pragma unroll
    for (int k0 = 0; k0 < F; k0 += 4) {
        if (k0 + 4 < F) {
#pragma unroll
            for (int r = 0; r < 4; r++)
                xn[r] = __ldg((const ulonglong2*)(feat
                              + (size_t)(row0t + r) * C4 + ((k0 + 4) >> 2)));
        }
#pragma unroll
        for (int c = 0; c < 6; c++) {
            ulonglong2 wv = *(const ulonglong2*)&Wt[WTOFF(colL0 + c, k0)];
#pragma unroll
            for (int r = 0; r < 4; r++) {
                fma2(acc[r * 6 + c], xv[r].x, wv.x);
                fma2(acc[r * 6 + c], xv[r].y, wv.y);
            }
        }
#pragma unroll
        for (int r = 0; r < 4; r++) xv[r] = xn[r];
    }
}

// ---------------------------------------------------------------------------
// launch 3: gemm1: g_h1s = relu(dinv .* (g_agg1 @ W1) + b1)   (unscaled out)
// gridDim = (gg, 2): y = column half. colhalf 0 re-zeroes g_degi for replay.
// ---------------------------------------------------------------------------
__global__ void __launch_bounds__(128) gemm1_kernel(
        const float* __restrict__ W, const float* __restrict__ b, int N) {
    __shared__ __align__(16) float Wt[WT_FLOATS];
    const int t = threadIdx.x;
    const int colhalf = blockIdx.y;
    const int row0 = blockIdx.x * GR;

    if (colhalf == 0) {
        int gi = blockIdx.x * 128 + t;
        if (gi < N) g_degi[gi] = 0;
    }
    load_wt_half(Wt, W, colhalf, t);
    __syncthreads();

    const int rowg = t >> 3, colg = t & 7;
    const int row0t = row0 + rowg * 4;
    const int colL0 = colg * 6;
    unsigned long long acc[24] = {};
    mmkern(Wt, g_agg1, row0t, colL0, acc);

    const int col0 = colhalf * 48 + colL0;
#pragma unroll
    for (int r = 0; r < 4; r++) {
        int row = row0t + r;
        if (row < N) {
            float dv = g_dinv[row];
            float* o = (float*)g_h1s + (size_t)row * F + col0;
#pragma unroll
            for (int q = 0; q < 3; q++) {
                float2 v;
                v.x = fmaxf(fmaf(dv, sum2(acc[r*6 + q*2 + 0]), b[col0 + q*2 + 0]), 0.f);
                v.y = fmaxf(fmaf(dv, sum2(acc[r*6 + q*2 + 1]), b[col0 + q*2 + 1]), 0.f);
                *(float2*)&o[q * 2] = v;
            }
        }
    }
}

// ---------------------------------------------------------------------------
// launch 5: dual GEMM, gridDim = (gg, 2): y = column half.
// Each block computes BOTH phases (mu then logstd) for its col-half;
// second phase's x reads hit L1 (24KB row working set stays resident).
// ---------------------------------------------------------------------------
__global__ void __launch_bounds__(128) gemm2_kernel(
        const float* __restrict__ Wa, const float* __restrict__ ba,
        const float* __restrict__ Wb, const float* __restrict__ bb,
        float* __restrict__ out, int N) {
    __shared__ __align__(16) float Wt[WT_FLOATS];
    const int t = threadIdx.x;
    const int colhalf = blockIdx.y;
    const int row0 = blockIdx.x * GR;

    const int rowg = t >> 3, colg = t & 7;
    const int row0t = row0 + rowg * 4;
    const int colL0 = colg * 6;
    const int col0 = colhalf * 48 + colL0;
    const size_t NF = (size_t)N * F;

    float dv[4];
#pragma unroll
    for (int r = 0; r < 4; r++)
        dv[r] = (row0t + r < N) ? g_dinv[row0t + r] : 0.f;

    // phase A: mu
    load_wt_half(Wt, Wa, colhalf, t);
    __syncthreads();
    {
        unsigned long long acc[24] = {};
        mmkern(Wt, g_agg2, row0t, colL0, acc);
#pragma unroll
        for (int r = 0; r < 4; r++) {
            int row = row0t + r;
            if (row < N) {
                size_t off = (size_t)row * F + col0;
#pragma unroll
                for (int q = 0; q < 3; q++) {
                    float2 v;
                    v.x = fmaf(dv[r], sum2(acc[r*6 + q*2 + 0]), ba[col0 + q*2 + 0]);
                    v.y = fmaf(dv[r], sum2(acc[r*6 + q*2 + 1]), ba[col0 + q*2 + 1]);
                    *(float2*)&out[off + q * 2] = v;
                }
            }
        }
    }

    // phase B: logstd
    __syncthreads();
    load_wt_half(Wt, Wb, colhalf, t);
    __syncthreads();
    {
        unsigned long long acc[24] = {};
        mmkern(Wt, g_agg2, row0t, colL0, acc);
#pragma unroll
        for (int r = 0; r < 4; r++) {
            int row = row0t + r;
            if (row < N) {
                size_t off = NF + (size_t)row * F + col0;
#pragma unroll
                for (int q = 0; q < 3; q++) {
                    float2 v;
                    v.x = fmaf(dv[r], sum2(acc[r*6 + q*2 + 0]), bb[col0 + q*2 + 0]);
                    v.y = fmaf(dv[r], sum2(acc[r*6 + q*2 + 1]), bb[col0 + q*2 + 1]);
                    *(float2*)&out[off + q * 2] = v;
                }
            }
        }
    }
}

// ---------------------------------------------------------------------------
// inputs: x, W1, b1, W2a, b2a, W2b, b2b, edge_index[2,E]
// output: concat(mu [N,F], logstd [N,F])
//
// A_norm = D^-1/2 A D^-1/2 and GCN linearity give:
//   GCN(x) = (dinv .* (A @ (dinv .* x))) @ W + b
// -> scatter multiplies by dinv[src] in-flight; dst-side dinv is factored out
//    of the GEMM dot product and applied in the epilogue.
// NOTE: no __device__ symbol is ever passed from host (ATS shadow-addr trap).
// ---------------------------------------------------------------------------
extern "C" void kernel_launch(void* const* d_in, const int* in_sizes, int n_in,
                              void* d_out, int out_size) {
    const float* x   = (const float*)d_in[0];
    const float* W1  = (const float*)d_in[1];
    const float* b1  = (const float*)d_in[2];
    const float* W2a = (const float*)d_in[3];
    const float* b2a = (const float*)d_in[4];
    const float* W2b = (const float*)d_in[5];
    const float* b2b = (const float*)d_in[6];
    const int*   ei  = (const int*)d_in[7];

    const int N = in_sizes[0] / F;
    const int E = in_sizes[7] / 2;
    const int* src = ei;
    const int* dst = ei + E;
    float* out = (float*)d_out;

    const int TB = 256;
    int eg  = (E + TB - 1) / TB;
    int ng  = (N + TB - 1) / TB;
    int sg  = (E + ET - 1) / ET;
    int gg  = (N + GR - 1) / GR;

    deg_kernel  <<<eg, TB>>>(dst, E, N);                    // 0 (+agg zeroing)
    dinv_kernel <<<ng, TB>>>(N);                            // 1
    scatter_kernel<false, 1><<<sg, 192>>>(src, dst,
                               (const float4*)x, E);        // 2: x   -> agg1
    gemm1_kernel<<<dim3(gg, 2), 128>>>(W1, b1, N);          // 3: -> h1s (+deg reset)
    scatter_kernel<true, 3><<<sg, 192>>>(src, dst, nullptr, E); // 4: h1s -> agg2
    gemm2_kernel<<<dim3(gg, 2), 128>>>(W2a, b2a, W2b, b2b, out, N); // 5
}